// round 2
// baseline (speedup 1.0000x reference)
#include <cuda_runtime.h>

#define N_NODES 100000
#define E_EDGES 1600000
#define ET_EDGES (E_EDGES + N_NODES)
#define F_IN 128
#define F1 256          // HEADS*HID
#define NHEADS 8
#define HIDC 32
#define NBLK_SCAN 98    // ceil(100000/1024)

// ---------------- device scratch (allocation-free rule: static globals) ----------------
__device__ __align__(16) float g_xh1[(size_t)N_NODES * F1];    // layer1 per-head features
__device__ __align__(16) float g_h1 [(size_t)N_NODES * F1];    // layer1 output (post relu)
__device__ __align__(16) float g_xh2[(size_t)N_NODES * HIDC];  // layer2 features
__device__ __align__(16) float g_esrc1[N_NODES * NHEADS];
__device__ __align__(16) float g_edst1[N_NODES * NHEADS];
__device__ float g_esrc2[N_NODES];
__device__ float g_edst2[N_NODES];
__device__ int g_deg[N_NODES];
__device__ int g_off[N_NODES + 1];
__device__ int g_cur[N_NODES];
__device__ int g_csr_src[ET_EDGES];
__device__ int g_bsum[128];
__device__ int g_boff[128];

// ---------------- CSR build ----------------
// NOTE: edge_index is int32 on device (JAX x64 disabled downgrades int64->int32).
__global__ void k_zero_deg() {
    int i = blockIdx.x * blockDim.x + threadIdx.x;
    if (i < N_NODES) g_deg[i] = 0;
}

__global__ void k_hist(const int* __restrict__ ei) {
    int e = blockIdx.x * blockDim.x + threadIdx.x;
    if (e >= ET_EDGES) return;
    int d = (e < E_EDGES) ? ei[E_EDGES + e] : (e - E_EDGES);
    d = min(max(d, 0), N_NODES - 1);   // safety clamp (branch-free)
    atomicAdd(&g_deg[d], 1);
}

__global__ void k_scan_part() {
    __shared__ int sm[1024];
    int i = blockIdx.x * 1024 + threadIdx.x;
    int v = (i < N_NODES) ? g_deg[i] : 0;
    sm[threadIdx.x] = v;
    __syncthreads();
    for (int ofs = 1; ofs < 1024; ofs <<= 1) {
        int t = (threadIdx.x >= ofs) ? sm[threadIdx.x - ofs] : 0;
        __syncthreads();
        sm[threadIdx.x] += t;
        __syncthreads();
    }
    if (i < N_NODES) g_off[i] = sm[threadIdx.x] - v;  // exclusive within block
    if (threadIdx.x == 1023) g_bsum[blockIdx.x] = sm[1023];
}

__global__ void k_scan_top(int nb) {
    if (threadIdx.x == 0) {
        int acc = 0;
        for (int b = 0; b < nb; b++) { g_boff[b] = acc; acc += g_bsum[b]; }
        g_off[N_NODES] = acc;  // == ET_EDGES
    }
}

__global__ void k_scan_add() {
    int i = blockIdx.x * 1024 + threadIdx.x;
    if (i < N_NODES) {
        int o = g_off[i] + g_boff[blockIdx.x];
        g_off[i] = o;
        g_cur[i] = o;
    }
}

__global__ void k_scatter(const int* __restrict__ ei) {
    int e = blockIdx.x * blockDim.x + threadIdx.x;
    if (e >= ET_EDGES) return;
    int s, d;
    if (e < E_EDGES) { s = ei[e]; d = ei[E_EDGES + e]; }
    else             { s = d = e - E_EDGES; }
    s = min(max(s, 0), N_NODES - 1);
    d = min(max(d, 0), N_NODES - 1);
    int p = atomicAdd(&g_cur[d], 1);
    if (p < ET_EDGES) g_csr_src[p] = s;
}

// ---------------- GEMM1: xh1 = x @ W1   [100000 x 128] @ [128 x 256] ----------------
// 256 threads. BM=32 rows per tile, full K=128, full N=256. W1 resident in smem.
// thread (tx = t&31, ty = t>>5): rows ty*4..ty*4+3, cols tx*8..tx*8+7.
#define G1_SMEM ((128 * 256 + 32 * 129) * 4)
__global__ void k_gemm1(const float* __restrict__ x, const float* __restrict__ W) {
    extern __shared__ float smem[];
    float* Wsm = smem;             // [128][256]
    float* xsm = smem + 128 * 256; // [32][129] padded
    const float4* W4 = (const float4*)W;
    for (int i = threadIdx.x; i < 128 * 256 / 4; i += 256)
        ((float4*)Wsm)[i] = W4[i];

    int tx = threadIdx.x & 31;
    int ty = threadIdx.x >> 5;
    int ty4 = ty * 4;
    const float4* x4 = (const float4*)x;

    for (int tile = blockIdx.x; tile < N_NODES / 32; tile += gridDim.x) {
        int row0 = tile * 32;
        __syncthreads();
        // stage 32 rows x 128 floats
        for (int i = threadIdx.x; i < 1024; i += 256) {
            int r = i >> 5, c4 = i & 31;
            float4 v = x4[(size_t)(row0 + r) * 32 + c4];
            float* xd = &xsm[r * 129 + (c4 << 2)];
            xd[0] = v.x; xd[1] = v.y; xd[2] = v.z; xd[3] = v.w;
        }
        __syncthreads();

        float acc[4][8];
        #pragma unroll
        for (int i = 0; i < 4; i++)
            #pragma unroll
            for (int j = 0; j < 8; j++) acc[i][j] = 0.f;

        #pragma unroll 8
        for (int k = 0; k < 128; k++) {
            float4 b0 = *(const float4*)&Wsm[k * 256 + (tx << 3)];
            float4 b1 = *(const float4*)&Wsm[k * 256 + (tx << 3) + 4];
            float a0 = xsm[(ty4 + 0) * 129 + k];
            float a1 = xsm[(ty4 + 1) * 129 + k];
            float a2 = xsm[(ty4 + 2) * 129 + k];
            float a3 = xsm[(ty4 + 3) * 129 + k];
            float a[4] = {a0, a1, a2, a3};
            #pragma unroll
            for (int i = 0; i < 4; i++) {
                acc[i][0] += a[i] * b0.x; acc[i][1] += a[i] * b0.y;
                acc[i][2] += a[i] * b0.z; acc[i][3] += a[i] * b0.w;
                acc[i][4] += a[i] * b1.x; acc[i][5] += a[i] * b1.y;
                acc[i][6] += a[i] * b1.z; acc[i][7] += a[i] * b1.w;
            }
        }
        #pragma unroll
        for (int i = 0; i < 4; i++) {
            int row = row0 + ty4 + i;
            float4 o0 = {acc[i][0], acc[i][1], acc[i][2], acc[i][3]};
            float4 o1 = {acc[i][4], acc[i][5], acc[i][6], acc[i][7]};
            float4* dst = (float4*)(g_xh1 + (size_t)row * F1) + (tx << 1);
            dst[0] = o0; dst[1] = o1;
        }
    }
}

// ---------------- attention coefficients, layer 1 ----------------
__global__ void k_attn1(const float* __restrict__ a_src, const float* __restrict__ a_dst) {
    int w = blockIdx.x * 8 + (threadIdx.x >> 5);
    if (w >= N_NODES) return;
    int lane = threadIdx.x & 31;
    int h = lane >> 2, q = lane & 3;
    int f4 = h * 8 + q * 2;
    const float4* row = (const float4*)(g_xh1 + (size_t)w * F1);
    float4 v0 = row[f4], v1 = row[f4 + 1];
    float4 s0 = __ldg((const float4*)a_src + f4), s1 = __ldg((const float4*)a_src + f4 + 1);
    float4 d0 = __ldg((const float4*)a_dst + f4), d1 = __ldg((const float4*)a_dst + f4 + 1);
    float es = v0.x*s0.x + v0.y*s0.y + v0.z*s0.z + v0.w*s0.w
             + v1.x*s1.x + v1.y*s1.y + v1.z*s1.z + v1.w*s1.w;
    float ed = v0.x*d0.x + v0.y*d0.y + v0.z*d0.z + v0.w*d0.w
             + v1.x*d1.x + v1.y*d1.y + v1.z*d1.z + v1.w*d1.w;
    es += __shfl_xor_sync(0xffffffffu, es, 1);
    es += __shfl_xor_sync(0xffffffffu, es, 2);
    ed += __shfl_xor_sync(0xffffffffu, ed, 1);
    ed += __shfl_xor_sync(0xffffffffu, ed, 2);
    if (q == 0) { g_esrc1[w * NHEADS + h] = es; g_edst1[w * NHEADS + h] = ed; }
}

// ---------------- aggregation layer 1: one warp per dst node ----------------
__global__ void k_agg1(const float* __restrict__ bias) {
    int d = blockIdx.x * 8 + (threadIdx.x >> 5);
    if (d >= N_NODES) return;
    int lane = threadIdx.x & 31;
    int beg = g_off[d], end = g_off[d + 1];
    int h = lane >> 2, q = lane & 3;
    float edh = __ldg(&g_edst1[d * NHEADS + h]);

    // pass A: per-head softmax denominator (no max-shift; e is bounded)
    float s = 0.f;
    for (int i = beg + q; i < end; i += 4) {
        int src = g_csr_src[i];
        float e = __ldg(&g_esrc1[src * NHEADS + h]) + edh;
        e = (e > 0.f) ? e : 0.2f * e;
        s += __expf(e);
    }
    s += __shfl_xor_sync(0xffffffffu, s, 1);
    s += __shfl_xor_sync(0xffffffffu, s, 2);
    float inv = 1.0f / s;

    // pass B: weighted aggregation; lane owns 8 contiguous channels (lane*8)
    float4 aA = {0,0,0,0}, aB = {0,0,0,0};
    for (int i = beg; i < end; i++) {
        int src = __ldg(&g_csr_src[i]);
        float e = __ldg(&g_esrc1[src * NHEADS + h]) + edh;
        e = (e > 0.f) ? e : 0.2f * e;
        float wgt = __expf(e) * inv;
        const float4* xr = (const float4*)(g_xh1 + (size_t)src * F1) + (lane << 1);
        float4 v0 = __ldg(xr), v1 = __ldg(xr + 1);
        aA.x += wgt * v0.x; aA.y += wgt * v0.y; aA.z += wgt * v0.z; aA.w += wgt * v0.w;
        aB.x += wgt * v1.x; aB.y += wgt * v1.y; aB.z += wgt * v1.z; aB.w += wgt * v1.w;
    }
    const float4* bb = (const float4*)bias + (lane << 1);
    float4 b0 = __ldg(bb), b1 = __ldg(bb + 1);
    float4 o0, o1;
    o0.x = fmaxf(aA.x + b0.x, 0.f); o0.y = fmaxf(aA.y + b0.y, 0.f);
    o0.z = fmaxf(aA.z + b0.z, 0.f); o0.w = fmaxf(aA.w + b0.w, 0.f);
    o1.x = fmaxf(aB.x + b1.x, 0.f); o1.y = fmaxf(aB.y + b1.y, 0.f);
    o1.z = fmaxf(aB.z + b1.z, 0.f); o1.w = fmaxf(aB.w + b1.w, 0.f);
    float4* dst = (float4*)(g_h1 + (size_t)d * F1) + (lane << 1);
    dst[0] = o0; dst[1] = o1;
}

// ---------------- GEMM2: xh2 = h1 @ W2   [100000 x 256] @ [256 x 32] ----------------
// 256 threads. BM=64 rows, full K=256, full N=32. tx=t&7 cols 4tx..; ty=t>>3 rows {ty, ty+32}
#define G2_SMEM ((256 * 32 + 64 * 257) * 4)
__global__ void k_gemm2(const float* __restrict__ W) {
    extern __shared__ float smem[];
    float* Wsm = smem;              // [256][32]
    float* xsm = smem + 256 * 32;   // [64][257]
    const float4* W4 = (const float4*)W;
    for (int i = threadIdx.x; i < 256 * 32 / 4; i += 256)
        ((float4*)Wsm)[i] = W4[i];

    int row0 = blockIdx.x * 64;
    const float4* x4 = (const float4*)g_h1;
    for (int i = threadIdx.x; i < 4096; i += 256) {  // 64 rows x 64 float4
        int r = i >> 6, c4 = i & 63;
        int row = row0 + r;
        float4 v = {0,0,0,0};
        if (row < N_NODES) v = x4[(size_t)row * 64 + c4];
        float* xd = &xsm[r * 257 + (c4 << 2)];
        xd[0] = v.x; xd[1] = v.y; xd[2] = v.z; xd[3] = v.w;
    }
    __syncthreads();

    int tx = threadIdx.x & 7;
    int ty = threadIdx.x >> 3;
    float acc0[4] = {0,0,0,0}, acc1[4] = {0,0,0,0};
    #pragma unroll 8
    for (int k = 0; k < 256; k++) {
        float4 b = *(const float4*)&Wsm[k * 32 + (tx << 2)];
        float a0 = xsm[ty * 257 + k];
        float a1 = xsm[(ty + 32) * 257 + k];
        acc0[0] += a0 * b.x; acc0[1] += a0 * b.y; acc0[2] += a0 * b.z; acc0[3] += a0 * b.w;
        acc1[0] += a1 * b.x; acc1[1] += a1 * b.y; acc1[2] += a1 * b.z; acc1[3] += a1 * b.w;
    }
    int r0 = row0 + ty, r1 = row0 + ty + 32;
    if (r0 < N_NODES) {
        float4 o = {acc0[0], acc0[1], acc0[2], acc0[3]};
        *((float4*)(g_xh2 + (size_t)r0 * HIDC) + tx) = o;
    }
    if (r1 < N_NODES) {
        float4 o = {acc1[0], acc1[1], acc1[2], acc1[3]};
        *((float4*)(g_xh2 + (size_t)r1 * HIDC) + tx) = o;
    }
}

// ---------------- attention coefficients, layer 2 (single head) ----------------
__global__ void k_attn2(const float* __restrict__ a_src, const float* __restrict__ a_dst) {
    int w = blockIdx.x * 8 + (threadIdx.x >> 5);
    if (w >= N_NODES) return;
    int lane = threadIdx.x & 31;
    float v = g_xh2[(size_t)w * HIDC + lane];
    float es = v * __ldg(&a_src[lane]);
    float ed = v * __ldg(&a_dst[lane]);
    #pragma unroll
    for (int o = 16; o; o >>= 1) {
        es += __shfl_xor_sync(0xffffffffu, es, o);
        ed += __shfl_xor_sync(0xffffffffu, ed, o);
    }
    if (lane == 0) { g_esrc2[w] = es; g_edst2[w] = ed; }
}

// ---------------- aggregation layer 2: one warp per dst node, writes d_out ----------------
__global__ void k_agg2(const float* __restrict__ bias, float* __restrict__ out) {
    int d = blockIdx.x * 8 + (threadIdx.x >> 5);
    if (d >= N_NODES) return;
    int lane = threadIdx.x & 31;
    int beg = g_off[d], end = g_off[d + 1];
    float edd = __ldg(&g_edst2[d]);
    float s = 0.f;
    for (int i = beg + lane; i < end; i += 32) {
        int src = g_csr_src[i];
        float e = __ldg(&g_esrc2[src]) + edd;
        e = (e > 0.f) ? e : 0.2f * e;
        s += __expf(e);
    }
    #pragma unroll
    for (int o = 16; o; o >>= 1) s += __shfl_xor_sync(0xffffffffu, s, o);
    float inv = 1.0f / s;
    float acc = 0.f;
    for (int i = beg; i < end; i++) {
        int src = __ldg(&g_csr_src[i]);
        float e = __ldg(&g_esrc2[src]) + edd;
        e = (e > 0.f) ? e : 0.2f * e;
        acc += __expf(e) * inv * __ldg(&g_xh2[(size_t)src * HIDC + lane]);
    }
    out[(size_t)d * HIDC + lane] = acc + __ldg(&bias[lane]);
}

// ---------------- host launch ----------------
extern "C" void kernel_launch(void* const* d_in, const int* in_sizes, int n_in,
                              void* d_out, int out_size) {
    const float* x      = (const float*)d_in[0];
    const int*   ei     = (const int*)d_in[1];   // int32! (JAX x64 disabled)
    const float* W1     = (const float*)d_in[2];
    const float* a_src1 = (const float*)d_in[3];
    const float* a_dst1 = (const float*)d_in[4];
    const float* b1     = (const float*)d_in[5];
    const float* W2     = (const float*)d_in[6];
    const float* a_src2 = (const float*)d_in[7];
    const float* a_dst2 = (const float*)d_in[8];
    const float* b2     = (const float*)d_in[9];
    float* out = (float*)d_out;

    cudaFuncSetAttribute(k_gemm1, cudaFuncAttributeMaxDynamicSharedMemorySize, G1_SMEM);
    cudaFuncSetAttribute(k_gemm2, cudaFuncAttributeMaxDynamicSharedMemorySize, G2_SMEM);

    // CSR build (independent of GEMM1; stream-serial for now)
    k_zero_deg<<<(N_NODES + 255) / 256, 256>>>();
    k_hist<<<(ET_EDGES + 255) / 256, 256>>>(ei);
    k_scan_part<<<NBLK_SCAN, 1024>>>();
    k_scan_top<<<1, 32>>>(NBLK_SCAN);
    k_scan_add<<<NBLK_SCAN, 1024>>>();
    k_scatter<<<(ET_EDGES + 255) / 256, 256>>>(ei);

    // layer 1
    k_gemm1<<<148, 256, G1_SMEM>>>(x, W1);
    k_attn1<<<N_NODES / 8, 256>>>(a_src1, a_dst1);
    k_agg1<<<N_NODES / 8, 256>>>(b1);

    // layer 2
    k_gemm2<<<(N_NODES + 63) / 64, 256, G2_SMEM>>>(W2);
    k_attn2<<<N_NODES / 8, 256>>>(a_src2, a_dst2);
    k_agg2<<<N_NODES / 8, 256>>>(b2, out);
}

// round 3
// speedup vs baseline: 1.0834x; 1.0834x over previous
#include <cuda_runtime.h>

#define N_NODES 100000
#define E_EDGES 1600000
#define ET_EDGES (E_EDGES + N_NODES)
#define F_IN 128
#define F1 256          // HEADS*HID
#define NHEADS 8
#define HIDC 32
#define NBLK_SCAN 98    // ceil(100000/1024)

// ---------------- device scratch ----------------
__device__ __align__(16) float g_xh1[(size_t)N_NODES * F1];
__device__ __align__(16) float g_h1 [(size_t)N_NODES * F1];
__device__ __align__(16) float g_xh2[(size_t)N_NODES * HIDC];
__device__ __align__(16) float g_esrc1[N_NODES * NHEADS];
__device__ __align__(16) float g_edst1[N_NODES * NHEADS];
__device__ float g_esrc2[N_NODES];
__device__ float g_edst2[N_NODES];
__device__ int g_deg[N_NODES];
__device__ int g_off[N_NODES + 1];
__device__ int g_cur[N_NODES];
__device__ int g_csr_src[ET_EDGES];
__device__ int g_bsum[128];
__device__ int g_boff[128];

// ---------------- packed f32x2 helpers (Blackwell sm_100+) ----------------
__device__ __forceinline__ unsigned long long pk2(float lo, float hi) {
    unsigned long long r;
    asm("mov.b64 %0, {%1, %2};" : "=l"(r) : "f"(lo), "f"(hi));
    return r;
}
__device__ __forceinline__ void fma2(unsigned long long& d,
                                     unsigned long long a, unsigned long long b) {
    asm("fma.rn.f32x2 %0, %1, %2, %0;" : "+l"(d) : "l"(a), "l"(b));
}
__device__ __forceinline__ float2 upk2(unsigned long long v) {
    float2 f;
    asm("mov.b64 {%0, %1}, %2;" : "=f"(f.x), "=f"(f.y) : "l"(v));
    return f;
}

// ---------------- CSR build (edge_index is int32) ----------------
__global__ void k_zero_deg() {
    int i = blockIdx.x * blockDim.x + threadIdx.x;
    if (i < N_NODES) g_deg[i] = 0;
}

__global__ void k_hist(const int* __restrict__ ei) {
    int e = blockIdx.x * blockDim.x + threadIdx.x;
    if (e >= ET_EDGES) return;
    int d = (e < E_EDGES) ? ei[E_EDGES + e] : (e - E_EDGES);
    d = min(max(d, 0), N_NODES - 1);
    atomicAdd(&g_deg[d], 1);
}

__global__ void k_scan_part() {
    __shared__ int sm[1024];
    int i = blockIdx.x * 1024 + threadIdx.x;
    int v = (i < N_NODES) ? g_deg[i] : 0;
    sm[threadIdx.x] = v;
    __syncthreads();
    for (int ofs = 1; ofs < 1024; ofs <<= 1) {
        int t = (threadIdx.x >= ofs) ? sm[threadIdx.x - ofs] : 0;
        __syncthreads();
        sm[threadIdx.x] += t;
        __syncthreads();
    }
    if (i < N_NODES) g_off[i] = sm[threadIdx.x] - v;
    if (threadIdx.x == 1023) g_bsum[blockIdx.x] = sm[1023];
}

__global__ void k_scan_top(int nb) {
    int lane = threadIdx.x;   // one warp
    int carry = 0;
    for (int base = 0; base < nb; base += 32) {
        int i = base + lane;
        int raw = (i < nb) ? g_bsum[i] : 0;
        int v = raw;
        #pragma unroll
        for (int o = 1; o < 32; o <<= 1) {
            int t = __shfl_up_sync(0xffffffffu, v, o);
            if (lane >= o) v += t;
        }
        if (i < nb) g_boff[i] = carry + v - raw;   // exclusive
        carry += __shfl_sync(0xffffffffu, v, 31);
    }
    if (lane == 0) g_off[N_NODES] = carry;
}

__global__ void k_scan_add() {
    int i = blockIdx.x * 1024 + threadIdx.x;
    if (i < N_NODES) {
        int o = g_off[i] + g_boff[blockIdx.x];
        g_off[i] = o;
        g_cur[i] = o;
    }
}

__global__ void k_scatter(const int* __restrict__ ei) {
    int e = blockIdx.x * blockDim.x + threadIdx.x;
    if (e >= ET_EDGES) return;
    int s, d;
    if (e < E_EDGES) { s = ei[e]; d = ei[E_EDGES + e]; }
    else             { s = d = e - E_EDGES; }
    s = min(max(s, 0), N_NODES - 1);
    d = min(max(d, 0), N_NODES - 1);
    int p = atomicAdd(&g_cur[d], 1);
    if (p < ET_EDGES) g_csr_src[p] = s;
}

// ---------------- GEMM1 + attn1 fused ----------------
// [100000 x 128] @ [128 x 256], W1 resident in smem, packed f32x2 FMA,
// register-staged x-tile prefetch, e_src1/e_dst1 computed in epilogue.
// 256 thr: tx=t&31 (cols tx*8..+7, all within head h=tx>>2), ty=t>>5 (rows ty*4..+3)
#define G1_SMEM ((128 * 256 + 32 * 129) * 4)
__global__ void k_gemm1(const float* __restrict__ x, const float* __restrict__ W,
                        const float* __restrict__ a_src, const float* __restrict__ a_dst) {
    extern __shared__ float smem[];
    float* Wsm = smem;             // [128][256]
    float* xsm = smem + 128 * 256; // [32][129]
    const float4* W4 = (const float4*)W;
    for (int i = threadIdx.x; i < 128 * 256 / 4; i += 256)
        ((float4*)Wsm)[i] = W4[i];

    const int tx = threadIdx.x & 31;
    const int ty = threadIdx.x >> 5;
    const int ty4 = ty * 4;
    const int h  = tx >> 2;        // head this thread's cols belong to
    const int q  = tx & 3;
    const float4* x4 = (const float4*)x;

    // per-thread attention vectors for its 8 cols
    float as[8], ad[8];
    #pragma unroll
    for (int j = 0; j < 8; j++) {
        as[j] = __ldg(&a_src[h * 32 + q * 8 + j]);
        ad[j] = __ldg(&a_dst[h * 32 + q * 8 + j]);
    }

    const int NT = N_NODES / 32;
    int tile = blockIdx.x;
    // prefetch first tile into regs
    float4 pre[4];
    if (tile < NT) {
        #pragma unroll
        for (int j = 0; j < 4; j++)
            pre[j] = x4[(size_t)tile * 1024 + threadIdx.x + j * 256];
    }

    for (; tile < NT; tile += gridDim.x) {
        __syncthreads();   // everyone done reading xsm from previous tile
        #pragma unroll
        for (int j = 0; j < 4; j++) {
            int idx = threadIdx.x + j * 256;
            int r = idx >> 5, c4 = idx & 31;
            float* xd = &xsm[r * 129 + (c4 << 2)];
            xd[0] = pre[j].x; xd[1] = pre[j].y; xd[2] = pre[j].z; xd[3] = pre[j].w;
        }
        __syncthreads();
        int nt = tile + gridDim.x;
        if (nt < NT) {     // prefetch next tile (latency hidden by compute)
            #pragma unroll
            for (int j = 0; j < 4; j++)
                pre[j] = x4[(size_t)nt * 1024 + threadIdx.x + j * 256];
        }

        unsigned long long acc2[4][4];
        #pragma unroll
        for (int i = 0; i < 4; i++)
            #pragma unroll
            for (int j = 0; j < 4; j++) acc2[i][j] = 0ull;

        #pragma unroll 4
        for (int k = 0; k < 128; k++) {
            ulonglong2 B0 = *(const ulonglong2*)&Wsm[k * 256 + (tx << 3)];
            ulonglong2 B1 = *(const ulonglong2*)&Wsm[k * 256 + (tx << 3) + 4];
            #pragma unroll
            for (int i = 0; i < 4; i++) {
                float a = xsm[(ty4 + i) * 129 + k];
                unsigned long long aa = pk2(a, a);
                fma2(acc2[i][0], aa, B0.x);
                fma2(acc2[i][1], aa, B0.y);
                fma2(acc2[i][2], aa, B1.x);
                fma2(acc2[i][3], aa, B1.y);
            }
        }

        int row0 = tile * 32;
        #pragma unroll
        for (int i = 0; i < 4; i++) {
            int row = row0 + ty4 + i;
            float2 c0 = upk2(acc2[i][0]), c1 = upk2(acc2[i][1]);
            float2 c2 = upk2(acc2[i][2]), c3 = upk2(acc2[i][3]);
            float4 o0 = {c0.x, c0.y, c1.x, c1.y};
            float4 o1 = {c2.x, c2.y, c3.x, c3.y};
            float4* dst = (float4*)(g_xh1 + (size_t)row * F1) + (tx << 1);
            dst[0] = o0; dst[1] = o1;
            // fused attn1: partial dot over this thread's 8 cols of head h
            float es = c0.x*as[0] + c0.y*as[1] + c1.x*as[2] + c1.y*as[3]
                     + c2.x*as[4] + c2.y*as[5] + c3.x*as[6] + c3.y*as[7];
            float ed = c0.x*ad[0] + c0.y*ad[1] + c1.x*ad[2] + c1.y*ad[3]
                     + c2.x*ad[4] + c2.y*ad[5] + c3.x*ad[6] + c3.y*ad[7];
            es += __shfl_xor_sync(0xffffffffu, es, 1);
            es += __shfl_xor_sync(0xffffffffu, es, 2);
            ed += __shfl_xor_sync(0xffffffffu, ed, 1);
            ed += __shfl_xor_sync(0xffffffffu, ed, 2);
            if (q == 0) {
                g_esrc1[row * NHEADS + h] = es;
                g_edst1[row * NHEADS + h] = ed;
            }
        }
    }
}

// ---------------- aggregation layer 1: one warp per dst node ----------------
__global__ void k_agg1(const float* __restrict__ bias) {
    int d = blockIdx.x * 8 + (threadIdx.x >> 5);
    if (d >= N_NODES) return;
    int lane = threadIdx.x & 31;
    int beg = g_off[d], end = g_off[d + 1];
    int h = lane >> 2, q = lane & 3;
    float edh = __ldg(&g_edst1[d * NHEADS + h]);

    // pass A: per-head softmax denominator (no max-shift; e is bounded)
    float s = 0.f;
    for (int i = beg + q; i < end; i += 4) {
        int src = g_csr_src[i];
        float e = __ldg(&g_esrc1[src * NHEADS + h]) + edh;
        e = (e > 0.f) ? e : 0.2f * e;
        s += __expf(e);
    }
    s += __shfl_xor_sync(0xffffffffu, s, 1);
    s += __shfl_xor_sync(0xffffffffu, s, 2);
    float inv = 1.0f / s;

    // pass B: weighted aggregation; lane owns 8 contiguous channels (lane*8)
    float4 aA = {0,0,0,0}, aB = {0,0,0,0};
    for (int i = beg; i < end; i++) {
        int src = __ldg(&g_csr_src[i]);
        float e = __ldg(&g_esrc1[src * NHEADS + h]) + edh;
        e = (e > 0.f) ? e : 0.2f * e;
        float wgt = __expf(e) * inv;
        const float4* xr = (const float4*)(g_xh1 + (size_t)src * F1) + (lane << 1);
        float4 v0 = __ldg(xr), v1 = __ldg(xr + 1);
        aA.x += wgt * v0.x; aA.y += wgt * v0.y; aA.z += wgt * v0.z; aA.w += wgt * v0.w;
        aB.x += wgt * v1.x; aB.y += wgt * v1.y; aB.z += wgt * v1.z; aB.w += wgt * v1.w;
    }
    const float4* bb = (const float4*)bias + (lane << 1);
    float4 b0 = __ldg(bb), b1 = __ldg(bb + 1);
    float4 o0, o1;
    o0.x = fmaxf(aA.x + b0.x, 0.f); o0.y = fmaxf(aA.y + b0.y, 0.f);
    o0.z = fmaxf(aA.z + b0.z, 0.f); o0.w = fmaxf(aA.w + b0.w, 0.f);
    o1.x = fmaxf(aB.x + b1.x, 0.f); o1.y = fmaxf(aB.y + b1.y, 0.f);
    o1.z = fmaxf(aB.z + b1.z, 0.f); o1.w = fmaxf(aB.w + b1.w, 0.f);
    float4* dst = (float4*)(g_h1 + (size_t)d * F1) + (lane << 1);
    dst[0] = o0; dst[1] = o1;
}

// ---------------- GEMM2 + attn2 fused ----------------
// [100000 x 256] @ [256 x 32]. tx=t&7 (cols tx*4..+3), ty=t>>3 (rows ty, ty+32)
#define G2_SMEM ((256 * 32 + 64 * 257) * 4)
__global__ void k_gemm2(const float* __restrict__ W,
                        const float* __restrict__ a_src, const float* __restrict__ a_dst) {
    extern __shared__ float smem[];
    float* Wsm = smem;              // [256][32]
    float* xsm = smem + 256 * 32;   // [64][257]
    const float4* W4 = (const float4*)W;
    for (int i = threadIdx.x; i < 256 * 32 / 4; i += 256)
        ((float4*)Wsm)[i] = W4[i];

    int row0 = blockIdx.x * 64;
    const float4* x4 = (const float4*)g_h1;
    for (int i = threadIdx.x; i < 4096; i += 256) {  // 64 rows x 64 float4
        int r = i >> 6, c4 = i & 63;
        int row = row0 + r;
        float4 v = {0,0,0,0};
        if (row < N_NODES) v = x4[(size_t)row * 64 + c4];
        float* xd = &xsm[r * 257 + (c4 << 2)];
        xd[0] = v.x; xd[1] = v.y; xd[2] = v.z; xd[3] = v.w;
    }
    __syncthreads();

    const int tx = threadIdx.x & 7;
    const int ty = threadIdx.x >> 3;
    float as[4], ad[4];
    #pragma unroll
    for (int j = 0; j < 4; j++) {
        as[j] = __ldg(&a_src[tx * 4 + j]);
        ad[j] = __ldg(&a_dst[tx * 4 + j]);
    }

    unsigned long long acc0[2] = {0ull, 0ull}, acc1[2] = {0ull, 0ull};
    #pragma unroll 8
    for (int k = 0; k < 256; k++) {
        ulonglong2 B = *(const ulonglong2*)&Wsm[k * 32 + (tx << 2)];
        float a0 = xsm[ty * 257 + k];
        float a1 = xsm[(ty + 32) * 257 + k];
        unsigned long long aa0 = pk2(a0, a0), aa1 = pk2(a1, a1);
        fma2(acc0[0], aa0, B.x); fma2(acc0[1], aa0, B.y);
        fma2(acc1[0], aa1, B.x); fma2(acc1[1], aa1, B.y);
    }

    #pragma unroll
    for (int half = 0; half < 2; half++) {
        int r = row0 + ty + half * 32;
        unsigned long long* acc = half ? acc1 : acc0;
        float2 c0 = upk2(acc[0]), c1 = upk2(acc[1]);
        if (r < N_NODES) {
            float4 o = {c0.x, c0.y, c1.x, c1.y};
            *((float4*)(g_xh2 + (size_t)r * HIDC) + tx) = o;
        }
        // fused attn2: dot over 32 cols (8 lanes x 4 cols), reduce within 8-lane group
        float es = c0.x*as[0] + c0.y*as[1] + c1.x*as[2] + c1.y*as[3];
        float ed = c0.x*ad[0] + c0.y*ad[1] + c1.x*ad[2] + c1.y*ad[3];
        es += __shfl_xor_sync(0xffffffffu, es, 1);
        es += __shfl_xor_sync(0xffffffffu, es, 2);
        es += __shfl_xor_sync(0xffffffffu, es, 4);
        ed += __shfl_xor_sync(0xffffffffu, ed, 1);
        ed += __shfl_xor_sync(0xffffffffu, ed, 2);
        ed += __shfl_xor_sync(0xffffffffu, ed, 4);
        if (tx == 0 && r < N_NODES) { g_esrc2[r] = es; g_edst2[r] = ed; }
    }
}

// ---------------- aggregation layer 2: one warp per dst node, writes d_out ----------------
__global__ void k_agg2(const float* __restrict__ bias, float* __restrict__ out) {
    int d = blockIdx.x * 8 + (threadIdx.x >> 5);
    if (d >= N_NODES) return;
    int lane = threadIdx.x & 31;
    int beg = g_off[d], end = g_off[d + 1];
    float edd = __ldg(&g_edst2[d]);
    float s = 0.f;
    for (int i = beg + lane; i < end; i += 32) {
        int src = g_csr_src[i];
        float e = __ldg(&g_esrc2[src]) + edd;
        e = (e > 0.f) ? e : 0.2f * e;
        s += __expf(e);
    }
    #pragma unroll
    for (int o = 16; o; o >>= 1) s += __shfl_xor_sync(0xffffffffu, s, o);
    float inv = 1.0f / s;
    float acc = 0.f;
    for (int i = beg; i < end; i++) {
        int src = __ldg(&g_csr_src[i]);
        float e = __ldg(&g_esrc2[src]) + edd;
        e = (e > 0.f) ? e : 0.2f * e;
        acc += __expf(e) * inv * __ldg(&g_xh2[(size_t)src * HIDC + lane]);
    }
    out[(size_t)d * HIDC + lane] = acc + __ldg(&bias[lane]);
}

// ---------------- host launch ----------------
extern "C" void kernel_launch(void* const* d_in, const int* in_sizes, int n_in,
                              void* d_out, int out_size) {
    const float* x      = (const float*)d_in[0];
    const int*   ei     = (const int*)d_in[1];   // int32 (JAX x64 disabled)
    const float* W1     = (const float*)d_in[2];
    const float* a_src1 = (const float*)d_in[3];
    const float* a_dst1 = (const float*)d_in[4];
    const float* b1     = (const float*)d_in[5];
    const float* W2     = (const float*)d_in[6];
    const float* a_src2 = (const float*)d_in[7];
    const float* a_dst2 = (const float*)d_in[8];
    const float* b2     = (const float*)d_in[9];
    float* out = (float*)d_out;

    cudaFuncSetAttribute(k_gemm1, cudaFuncAttributeMaxDynamicSharedMemorySize, G1_SMEM);
    cudaFuncSetAttribute(k_gemm2, cudaFuncAttributeMaxDynamicSharedMemorySize, G2_SMEM);

    // CSR build
    k_zero_deg<<<(N_NODES + 255) / 256, 256>>>();
    k_hist<<<(ET_EDGES + 255) / 256, 256>>>(ei);
    k_scan_part<<<NBLK_SCAN, 1024>>>();
    k_scan_top<<<1, 32>>>(NBLK_SCAN);
    k_scan_add<<<NBLK_SCAN, 1024>>>();
    k_scatter<<<(ET_EDGES + 255) / 256, 256>>>(ei);

    // layer 1
    k_gemm1<<<148, 256, G1_SMEM>>>(x, W1, a_src1, a_dst1);
    k_agg1<<<N_NODES / 8, 256>>>(b1);

    // layer 2
    k_gemm2<<<(N_NODES + 63) / 64, 256, G2_SMEM>>>(W2, a_src2, a_dst2);
    k_agg2<<<N_NODES / 8, 256>>>(b2, out);
}

// round 4
// speedup vs baseline: 1.2993x; 1.1993x over previous
#include <cuda_runtime.h>
#include <cuda_fp16.h>

#define N_NODES 100000
#define E_EDGES 1600000
#define ET_EDGES (E_EDGES + N_NODES)
#define F_IN 128
#define F1 256          // HEADS*HID
#define NHEADS 8
#define HIDC 32
#define NBLK_SCAN 98    // ceil(100000/1024)

// ---------------- device scratch ----------------
__device__ __align__(16) __half g_xh1h[(size_t)N_NODES * F1];  // fp16 layer1 features (gather table)
__device__ __align__(16) float g_h1 [(size_t)N_NODES * F1];    // layer1 output f32
__device__ __align__(16) float g_xh2[(size_t)N_NODES * HIDC];
__device__ __align__(16) float g_esrc1[N_NODES * NHEADS];
__device__ __align__(16) float g_edst1[N_NODES * NHEADS];
__device__ float g_esrc2[N_NODES];
__device__ float g_edst2[N_NODES];
__device__ int g_deg[N_NODES];
__device__ int g_off[N_NODES + 1];
__device__ int g_cur[N_NODES];
__device__ int g_csr_src[ET_EDGES];
__device__ int g_bsum[128];
__device__ int g_boff[128];

// ---------------- packed f32x2 + cp.async helpers ----------------
__device__ __forceinline__ unsigned long long pk2(float lo, float hi) {
    unsigned long long r;
    asm("mov.b64 %0, {%1, %2};" : "=l"(r) : "f"(lo), "f"(hi));
    return r;
}
__device__ __forceinline__ void fma2(unsigned long long& d,
                                     unsigned long long a, unsigned long long b) {
    asm("fma.rn.f32x2 %0, %1, %2, %0;" : "+l"(d) : "l"(a), "l"(b));
}
__device__ __forceinline__ float2 upk2(unsigned long long v) {
    float2 f;
    asm("mov.b64 {%0, %1}, %2;" : "=f"(f.x), "=f"(f.y) : "l"(v));
    return f;
}
__device__ __forceinline__ void cpa16(unsigned int saddr, const void* g) {
    asm volatile("cp.async.ca.shared.global [%0], [%1], 16;" :: "r"(saddr), "l"(g));
}
#define CPA_COMMIT() asm volatile("cp.async.commit_group;")
#define CPA_WAIT0()  asm volatile("cp.async.wait_group 0;")

// ---------------- CSR build (edge_index is int32) ----------------
__global__ void k_zero_deg() {
    int i = blockIdx.x * blockDim.x + threadIdx.x;
    if (i < N_NODES) g_deg[i] = 0;
}

__global__ void k_hist(const int* __restrict__ ei) {
    int e = blockIdx.x * blockDim.x + threadIdx.x;
    if (e >= ET_EDGES) return;
    int d = (e < E_EDGES) ? ei[E_EDGES + e] : (e - E_EDGES);
    d = min(max(d, 0), N_NODES - 1);
    atomicAdd(&g_deg[d], 1);
}

__global__ void k_scan_part() {
    __shared__ int sm[1024];
    int i = blockIdx.x * 1024 + threadIdx.x;
    int v = (i < N_NODES) ? g_deg[i] : 0;
    sm[threadIdx.x] = v;
    __syncthreads();
    for (int ofs = 1; ofs < 1024; ofs <<= 1) {
        int t = (threadIdx.x >= ofs) ? sm[threadIdx.x - ofs] : 0;
        __syncthreads();
        sm[threadIdx.x] += t;
        __syncthreads();
    }
    if (i < N_NODES) g_off[i] = sm[threadIdx.x] - v;
    if (threadIdx.x == 1023) g_bsum[blockIdx.x] = sm[1023];
}

__global__ void k_scan_top(int nb) {
    int lane = threadIdx.x;   // one warp
    int carry = 0;
    for (int base = 0; base < nb; base += 32) {
        int i = base + lane;
        int raw = (i < nb) ? g_bsum[i] : 0;
        int v = raw;
        #pragma unroll
        for (int o = 1; o < 32; o <<= 1) {
            int t = __shfl_up_sync(0xffffffffu, v, o);
            if (lane >= o) v += t;
        }
        if (i < nb) g_boff[i] = carry + v - raw;
        carry += __shfl_sync(0xffffffffu, v, 31);
    }
    if (lane == 0) g_off[N_NODES] = carry;
}

__global__ void k_scan_add() {
    int i = blockIdx.x * 1024 + threadIdx.x;
    if (i < N_NODES) {
        int o = g_off[i] + g_boff[blockIdx.x];
        g_off[i] = o;
        g_cur[i] = o;
    }
}

__global__ void k_scatter(const int* __restrict__ ei) {
    int e = blockIdx.x * blockDim.x + threadIdx.x;
    if (e >= ET_EDGES) return;
    int s, d;
    if (e < E_EDGES) { s = ei[e]; d = ei[E_EDGES + e]; }
    else             { s = d = e - E_EDGES; }
    s = min(max(s, 0), N_NODES - 1);
    d = min(max(d, 0), N_NODES - 1);
    int p = atomicAdd(&g_cur[d], 1);
    if (p < ET_EDGES) g_csr_src[p] = s;
}

// ---------------- GEMM1 + attn1 fused, fp16 output ----------------
// [100000 x 128] @ [128 x 256]. 128 threads: tx=t&31 (cols tx*8..+7), ty=t>>5 (rows ty*8..+7).
// W1 resident in smem; x tiles double-buffered via cp.async. Epilogue: fp16 store + attn dots.
#define G1_PAD 132
#define G1_SMEM ((128 * 256 + 2 * 32 * G1_PAD) * 4)
__global__ void k_gemm1(const float* __restrict__ x, const float* __restrict__ W,
                        const float* __restrict__ a_src, const float* __restrict__ a_dst) {
    extern __shared__ float smem[];
    float* Wsm = smem;                       // [128][256]
    float* xs0 = smem + 128 * 256;           // [32][G1_PAD] buf0
    float* xs1 = xs0 + 32 * G1_PAD;          // buf1
    const float4* W4 = (const float4*)W;
    for (int i = threadIdx.x; i < 128 * 256 / 4; i += 128)
        ((float4*)Wsm)[i] = W4[i];

    const int tx = threadIdx.x & 31;
    const int ty = threadIdx.x >> 5;
    const int h  = tx >> 2;
    const int q  = tx & 3;
    const float4* x4 = (const float4*)x;
    unsigned int sx[2];
    sx[0] = (unsigned int)__cvta_generic_to_shared(xs0);
    sx[1] = (unsigned int)__cvta_generic_to_shared(xs1);

    float as[8], ad[8];
    #pragma unroll
    for (int j = 0; j < 8; j++) {
        as[j] = __ldg(&a_src[tx * 8 + j]);
        ad[j] = __ldg(&a_dst[tx * 8 + j]);
    }

    const int NT = N_NODES / 32;
    int tile = blockIdx.x;
    // stage first tile into buf0
    if (tile < NT) {
        #pragma unroll
        for (int j = 0; j < 8; j++) {
            int idx = threadIdx.x + j * 128;
            int r = idx >> 5, c4 = idx & 31;
            cpa16(sx[0] + (unsigned)(r * G1_PAD + c4 * 4) * 4,
                  x4 + (size_t)tile * 1024 + idx);
        }
        CPA_COMMIT();
    }
    __syncthreads();   // W load done (also orders first-stage smem writes vs. nothing)

    int buf = 0;
    for (; tile < NT; tile += gridDim.x, buf ^= 1) {
        CPA_WAIT0();
        __syncthreads();           // current buf ready; all warps done with prev compute
        int nt = tile + gridDim.x;
        if (nt < NT) {             // stage next tile into other buffer
            #pragma unroll
            for (int j = 0; j < 8; j++) {
                int idx = threadIdx.x + j * 128;
                int r = idx >> 5, c4 = idx & 31;
                cpa16(sx[buf ^ 1] + (unsigned)(r * G1_PAD + c4 * 4) * 4,
                      x4 + (size_t)nt * 1024 + idx);
            }
            CPA_COMMIT();
        }
        const float* xb = buf ? xs1 : xs0;

        unsigned long long acc2[8][4];
        #pragma unroll
        for (int i = 0; i < 8; i++)
            #pragma unroll
            for (int j = 0; j < 4; j++) acc2[i][j] = 0ull;

        #pragma unroll 2
        for (int k = 0; k < 128; k++) {
            ulonglong2 B0 = *(const ulonglong2*)&Wsm[k * 256 + (tx << 3)];
            ulonglong2 B1 = *(const ulonglong2*)&Wsm[k * 256 + (tx << 3) + 4];
            #pragma unroll
            for (int i = 0; i < 8; i++) {
                float a = xb[(ty * 8 + i) * G1_PAD + k];
                unsigned long long aa = pk2(a, a);
                fma2(acc2[i][0], aa, B0.x);
                fma2(acc2[i][1], aa, B0.y);
                fma2(acc2[i][2], aa, B1.x);
                fma2(acc2[i][3], aa, B1.y);
            }
        }

        int row0 = tile * 32;
        #pragma unroll
        for (int i = 0; i < 8; i++) {
            int row = row0 + ty * 8 + i;
            float2 c0 = upk2(acc2[i][0]), c1 = upk2(acc2[i][1]);
            float2 c2 = upk2(acc2[i][2]), c3 = upk2(acc2[i][3]);
            // fp16 store of this thread's 8 cols (16B)
            __half2 h0 = __float22half2_rn(c0), h1 = __float22half2_rn(c1);
            __half2 h2 = __float22half2_rn(c2), h3 = __float22half2_rn(c3);
            uint4 st;
            st.x = *(unsigned int*)&h0; st.y = *(unsigned int*)&h1;
            st.z = *(unsigned int*)&h2; st.w = *(unsigned int*)&h3;
            ((uint4*)(g_xh1h + (size_t)row * F1))[tx] = st;
            // fused attn1 from exact f32 accumulators
            float es = c0.x*as[0] + c0.y*as[1] + c1.x*as[2] + c1.y*as[3]
                     + c2.x*as[4] + c2.y*as[5] + c3.x*as[6] + c3.y*as[7];
            float ed = c0.x*ad[0] + c0.y*ad[1] + c1.x*ad[2] + c1.y*ad[3]
                     + c2.x*ad[4] + c2.y*ad[5] + c3.x*ad[6] + c3.y*ad[7];
            es += __shfl_xor_sync(0xffffffffu, es, 1);
            es += __shfl_xor_sync(0xffffffffu, es, 2);
            ed += __shfl_xor_sync(0xffffffffu, ed, 1);
            ed += __shfl_xor_sync(0xffffffffu, ed, 2);
            if (q == 0) {
                g_esrc1[row * NHEADS + h] = es;
                g_edst1[row * NHEADS + h] = ed;
            }
        }
    }
}

// ---------------- aggregation layer 1: one warp per dst node, fp16 gather ----------------
__global__ void k_agg1(const float* __restrict__ bias) {
    int d = blockIdx.x * 8 + (threadIdx.x >> 5);
    if (d >= N_NODES) return;
    int lane = threadIdx.x & 31;
    int beg = g_off[d], end = g_off[d + 1];
    int h = lane >> 2, q = lane & 3;
    float edh = __ldg(&g_edst1[d * NHEADS + h]);

    // pass A: per-head softmax denominator
    float s = 0.f;
    for (int i = beg + q; i < end; i += 4) {
        int src = g_csr_src[i];
        float e = __ldg(&g_esrc1[src * NHEADS + h]) + edh;
        e = (e > 0.f) ? e : 0.2f * e;
        s += __expf(e);
    }
    s += __shfl_xor_sync(0xffffffffu, s, 1);
    s += __shfl_xor_sync(0xffffffffu, s, 2);
    float inv = 1.0f / s;

    // pass B: weighted fp16 gather; lane owns 8 contiguous channels (lane*8)
    float a0=0,a1=0,a2=0,a3=0,a4=0,a5=0,a6=0,a7=0;
    for (int i = beg; i < end; i++) {
        int src = __ldg(&g_csr_src[i]);
        float e = __ldg(&g_esrc1[src * NHEADS + h]) + edh;
        e = (e > 0.f) ? e : 0.2f * e;
        float wgt = __expf(e) * inv;
        uint4 v = __ldg((const uint4*)(g_xh1h + (size_t)src * F1) + lane);
        float2 f0 = __half22float2(*(const __half2*)&v.x);
        float2 f1 = __half22float2(*(const __half2*)&v.y);
        float2 f2 = __half22float2(*(const __half2*)&v.z);
        float2 f3 = __half22float2(*(const __half2*)&v.w);
        a0 += wgt * f0.x; a1 += wgt * f0.y; a2 += wgt * f1.x; a3 += wgt * f1.y;
        a4 += wgt * f2.x; a5 += wgt * f2.y; a6 += wgt * f3.x; a7 += wgt * f3.y;
    }
    const float4* bb = (const float4*)bias + (lane << 1);
    float4 b0 = __ldg(bb), b1 = __ldg(bb + 1);
    float4 o0, o1;
    o0.x = fmaxf(a0 + b0.x, 0.f); o0.y = fmaxf(a1 + b0.y, 0.f);
    o0.z = fmaxf(a2 + b0.z, 0.f); o0.w = fmaxf(a3 + b0.w, 0.f);
    o1.x = fmaxf(a4 + b1.x, 0.f); o1.y = fmaxf(a5 + b1.y, 0.f);
    o1.z = fmaxf(a6 + b1.z, 0.f); o1.w = fmaxf(a7 + b1.w, 0.f);
    float4* dst = (float4*)(g_h1 + (size_t)d * F1) + (lane << 1);
    dst[0] = o0; dst[1] = o1;
}

// ---------------- GEMM2 + attn2 fused ----------------
#define G2_SMEM ((256 * 32 + 64 * 257) * 4)
__global__ void k_gemm2(const float* __restrict__ W,
                        const float* __restrict__ a_src, const float* __restrict__ a_dst) {
    extern __shared__ float smem[];
    float* Wsm = smem;              // [256][32]
    float* xsm = smem + 256 * 32;   // [64][257]
    const float4* W4 = (const float4*)W;
    for (int i = threadIdx.x; i < 256 * 32 / 4; i += 256)
        ((float4*)Wsm)[i] = W4[i];

    int row0 = blockIdx.x * 64;
    const float4* x4 = (const float4*)g_h1;
    for (int i = threadIdx.x; i < 4096; i += 256) {
        int r = i >> 6, c4 = i & 63;
        int row = row0 + r;
        float4 v = {0,0,0,0};
        if (row < N_NODES) v = x4[(size_t)row * 64 + c4];
        float* xd = &xsm[r * 257 + (c4 << 2)];
        xd[0] = v.x; xd[1] = v.y; xd[2] = v.z; xd[3] = v.w;
    }
    __syncthreads();

    const int tx = threadIdx.x & 7;
    const int ty = threadIdx.x >> 3;
    float as[4], ad[4];
    #pragma unroll
    for (int j = 0; j < 4; j++) {
        as[j] = __ldg(&a_src[tx * 4 + j]);
        ad[j] = __ldg(&a_dst[tx * 4 + j]);
    }

    unsigned long long acc0[2] = {0ull, 0ull}, acc1[2] = {0ull, 0ull};
    #pragma unroll 8
    for (int k = 0; k < 256; k++) {
        ulonglong2 B = *(const ulonglong2*)&Wsm[k * 32 + (tx << 2)];
        float a0 = xsm[ty * 257 + k];
        float a1 = xsm[(ty + 32) * 257 + k];
        unsigned long long aa0 = pk2(a0, a0), aa1 = pk2(a1, a1);
        fma2(acc0[0], aa0, B.x); fma2(acc0[1], aa0, B.y);
        fma2(acc1[0], aa1, B.x); fma2(acc1[1], aa1, B.y);
    }

    #pragma unroll
    for (int half = 0; half < 2; half++) {
        int r = row0 + ty + half * 32;
        unsigned long long* acc = half ? acc1 : acc0;
        float2 c0 = upk2(acc[0]), c1 = upk2(acc[1]);
        if (r < N_NODES) {
            float4 o = {c0.x, c0.y, c1.x, c1.y};
            *((float4*)(g_xh2 + (size_t)r * HIDC) + tx) = o;
        }
        float es = c0.x*as[0] + c0.y*as[1] + c1.x*as[2] + c1.y*as[3];
        float ed = c0.x*ad[0] + c0.y*ad[1] + c1.x*ad[2] + c1.y*ad[3];
        es += __shfl_xor_sync(0xffffffffu, es, 1);
        es += __shfl_xor_sync(0xffffffffu, es, 2);
        es += __shfl_xor_sync(0xffffffffu, es, 4);
        ed += __shfl_xor_sync(0xffffffffu, ed, 1);
        ed += __shfl_xor_sync(0xffffffffu, ed, 2);
        ed += __shfl_xor_sync(0xffffffffu, ed, 4);
        if (tx == 0 && r < N_NODES) { g_esrc2[r] = es; g_edst2[r] = ed; }
    }
}

// ---------------- aggregation layer 2 ----------------
__global__ void k_agg2(const float* __restrict__ bias, float* __restrict__ out) {
    int d = blockIdx.x * 8 + (threadIdx.x >> 5);
    if (d >= N_NODES) return;
    int lane = threadIdx.x & 31;
    int beg = g_off[d], end = g_off[d + 1];
    float edd = __ldg(&g_edst2[d]);
    float s = 0.f;
    for (int i = beg + lane; i < end; i += 32) {
        int src = g_csr_src[i];
        float e = __ldg(&g_esrc2[src]) + edd;
        e = (e > 0.f) ? e : 0.2f * e;
        s += __expf(e);
    }
    #pragma unroll
    for (int o = 16; o; o >>= 1) s += __shfl_xor_sync(0xffffffffu, s, o);
    float inv = 1.0f / s;
    float acc = 0.f;
    for (int i = beg; i < end; i++) {
        int src = __ldg(&g_csr_src[i]);
        float e = __ldg(&g_esrc2[src]) + edd;
        e = (e > 0.f) ? e : 0.2f * e;
        acc += __expf(e) * inv * __ldg(&g_xh2[(size_t)src * HIDC + lane]);
    }
    out[(size_t)d * HIDC + lane] = acc + __ldg(&bias[lane]);
}

// ---------------- host launch ----------------
extern "C" void kernel_launch(void* const* d_in, const int* in_sizes, int n_in,
                              void* d_out, int out_size) {
    const float* x      = (const float*)d_in[0];
    const int*   ei     = (const int*)d_in[1];   // int32 (JAX x64 disabled)
    const float* W1     = (const float*)d_in[2];
    const float* a_src1 = (const float*)d_in[3];
    const float* a_dst1 = (const float*)d_in[4];
    const float* b1     = (const float*)d_in[5];
    const float* W2     = (const float*)d_in[6];
    const float* a_src2 = (const float*)d_in[7];
    const float* a_dst2 = (const float*)d_in[8];
    const float* b2     = (const float*)d_in[9];
    float* out = (float*)d_out;

    cudaFuncSetAttribute(k_gemm1, cudaFuncAttributeMaxDynamicSharedMemorySize, G1_SMEM);
    cudaFuncSetAttribute(k_gemm2, cudaFuncAttributeMaxDynamicSharedMemorySize, G2_SMEM);

    // CSR build
    k_zero_deg<<<(N_NODES + 255) / 256, 256>>>();
    k_hist<<<(ET_EDGES + 255) / 256, 256>>>(ei);
    k_scan_part<<<NBLK_SCAN, 1024>>>();
    k_scan_top<<<1, 32>>>(NBLK_SCAN);
    k_scan_add<<<NBLK_SCAN, 1024>>>();
    k_scatter<<<(ET_EDGES + 255) / 256, 256>>>(ei);

    // layer 1
    k_gemm1<<<148, 128, G1_SMEM>>>(x, W1, a_src1, a_dst1);
    k_agg1<<<N_NODES / 8, 256>>>(b1);

    // layer 2
    k_gemm2<<<(N_NODES + 63) / 64, 256, G2_SMEM>>>(W2, a_src2, a_dst2);
    k_agg2<<<N_NODES / 8, 256>>>(b2, out);
}